// round 17
// baseline (speedup 1.0000x reference)
#include <cuda_runtime.h>
#include <cuda_fp16.h>
#include <cstdint>

// Layout after transpose: per point n, 256 bytes = 16 chunks of 16B.
// Chunk f (f=0..15) = [ x(4f..4f+3) | y(4f..4f+3) ]  (8 halves).
// One edge endpoint = one contiguous 256B row = one LDG.128 across 16 lanes.
#define MAX_N 100000
#define E_PAD 240000   // >= 2*(P + 2*nwarps)+1 lookahead; pad records => 0
__device__ __align__(256) __half2 g_buf[(size_t)MAX_N * 64];
// Edge record: {s0*256, s1*256, half2(c,c) bits, 0}
__device__ __align__(16) uint4 g_edges[E_PAD];

__device__ __forceinline__ __half2 u2h(unsigned w) { return *(__half2*)&w; }

// ---------------- Kernel 1: transpose + edge-record prep ----------------
// Blocks [0, tblocks): transpose [64, N] float2 -> chunked half g_buf.
// Blocks [tblocks, ...): skeleton (int64 OR int32) + init_len -> padded
// pre-scaled records with c packed as half2. Dtype detect via ballot.
__global__ void __launch_bounds__(256) transpose_kernel(
    const float2* __restrict__ in, const unsigned* __restrict__ skel_raw,
    const float* __restrict__ init_len, float* out, int N, int E, int tblocks) {
    if (blockIdx.x >= tblocks) {
        // ---- prep branch ----
        __shared__ int sh_is64;
        if (threadIdx.x < 32) {
            unsigned v = skel_raw[2 * threadIdx.x + 1] |
                         skel_raw[2 * (threadIdx.x + 32) + 1];
            unsigned b = __ballot_sync(0xffffffffu, v == 0u);
            if (threadIdx.x == 0) sh_is64 = (b == 0xffffffffu);
        }
        __syncthreads();
        int is64 = sh_is64;
        int e = (blockIdx.x - tblocks) * 256 + threadIdx.x;
        if (e == 0) out[0] = 0.0f;
        if (e < E_PAD) {
            uint4 r = make_uint4(0u, 0u, 0u, 0u);
            if (e < E) {
                int s0, s1;
                if (is64) {
                    longlong2 s = ((const longlong2*)skel_raw)[e];
                    s0 = (int)s.x; s1 = (int)s.y;
                } else {
                    int2 s = ((const int2*)skel_raw)[e];
                    s0 = s.x; s1 = s.y;
                }
                r.x = (unsigned)s0 * 256u;
                r.y = (unsigned)s1 * 256u;
                unsigned hb = (unsigned)__half_as_ushort(__float2half_rn(init_len[e]));
                r.z = hb | (hb << 16);
            }
            g_edges[e] = r;
        }
        return;
    }

    // ---- transpose branch ----
    __shared__ float2 tile[64][33];
    int n0 = blockIdx.x * 32;
    int tx = threadIdx.x & 31;
    int ty = threadIdx.x >> 5;
    int c = n0 + tx;
    if (c < N) {
#pragma unroll
        for (int i = 0; i < 8; ++i) {
            int b = ty + i * 8;  // frame index 0..63
            tile[b][tx] = __ldcs(&in[(size_t)b * N + c]);
        }
    }
    __syncthreads();
#pragma unroll
    for (int k = 0; k < 4; ++k) {
        int l = threadIdx.x + k * 256;
        int bp = l & 31;      // frame pair: frames 2bp, 2bp+1
        int cc = l >> 5;      // point within block
        int n = n0 + cc;
        if (n < N) {
            float2 v0 = tile[2 * bp][cc];
            float2 v1 = tile[2 * bp + 1][cc];
            char* base = (char*)g_buf + (size_t)n * 256 + (bp >> 1) * 16 + (bp & 1) * 4;
            *(__half2*)(base)     = __floats2half2_rn(v0.x, v1.x);  // x pair
            *(__half2*)(base + 8) = __floats2half2_rn(v0.y, v1.y);  // y pair
        }
    }
}

// ---------------- Kernel 2: main loss ----------------
// Warp = 2 edges (16 lanes each). Lane covers 4 frames via ONE uint4 chunk
// per endpoint => 2 gather LDG.128 + 1 record LDG.128 per warp-iter.
// Depth-2 register pipeline. ENTIRE inner datapath in half2:
//   d = hsub2(h2sqrt(dx^2+dy^2), c_h2);  acc_h = hfma2(d, d, acc_h)
// No f32 conversion, no 64-bit math in the loop. Per-thread half acc tops
// out ~30 (fp16-safe); converted to f32 once at the end.
// Padded records (o=0, c=0) contribute sqrt(0)-0 squared = 0 exactly.

struct Rec { unsigned o0, o1, ch; };
struct GatherC { uint4 a, b; };  // 8 regs

__device__ __forceinline__ Rec load_rec(int e) {
    uint4 r = g_edges[e];
    Rec q;
    q.o0 = r.x;
    q.o1 = r.y;
    q.ch = r.z;
    return q;
}

__device__ __forceinline__ GatherC issue_gather(const char* tb, Rec q) {
    GatherC g;
    g.a = *(const uint4*)(tb + q.o0);
    g.b = *(const uint4*)(tb + q.o1);
    return g;
}

__global__ void __launch_bounds__(256, 6) loss_kernel(
    float* out, int E, float invE) {
    int lane = threadIdx.x & 31;
    int half = lane >> 4;      // which of 2 edges in warp
    int el = lane & 15;        // chunk index within row
    int warp = (blockIdx.x * blockDim.x + threadIdx.x) >> 5;
    int nwarps = (gridDim.x * blockDim.x) >> 5;
    int P = (E + 1) >> 1;
    const char* tb = (const char*)g_buf + (unsigned)el * 16u;

    __half2 acc_h = __float2half2_rn(0.0f);

    // Depth-2 prologue: record+gathers for p; record for p+nw.
    int p = warp;
    Rec qc = load_rec(2 * p + half);
    GatherC gc = issue_gather(tb, qc);
    Rec qn = load_rec(2 * (p + nwarps) + half);

#pragma unroll 2
    for (; p < P; p += nwarps) {
        // Issue next iteration's gathers (record already resident).
        GatherC gn = issue_gather(tb, qn);
        // Load record two iterations ahead (always in-bounds: E_PAD pad).
        Rec qf = load_rec(2 * (p + 2 * nwarps) + half);

        // Compute on current gathers (in flight since previous iteration).
        __half2 ch2 = u2h(qc.ch);
        const __half2* A = (const __half2*)&gc.a;  // [x01, x23, y01, y23]
        const __half2* B = (const __half2*)&gc.b;
        __half2 dx01 = __hsub2(A[0], B[0]);
        __half2 dx23 = __hsub2(A[1], B[1]);
        __half2 dy01 = __hsub2(A[2], B[2]);
        __half2 dy23 = __hsub2(A[3], B[3]);
        __half2 t01 = __hfma2(dy01, dy01, __hmul2(dx01, dx01));
        __half2 t23 = __hfma2(dy23, dy23, __hmul2(dx23, dx23));
        __half2 l01 = h2sqrt(t01);            // sqrt.approx.f16x2
        __half2 l23 = h2sqrt(t23);
        __half2 d01 = __hsub2(l01, ch2);
        __half2 d23 = __hsub2(l23, ch2);
        acc_h = __hfma2(d01, d01, acc_h);
        acc_h = __hfma2(d23, d23, acc_h);

        // Rotate (renamed under unroll).
        qc = qn;
        qn = qf;
        gc = gn;
    }

    float2 af = __half22float2(acc_h);
    float s = af.x + af.y;
#pragma unroll
    for (int off = 16; off; off >>= 1)
        s += __shfl_down_sync(0xffffffffu, s, off);

    __shared__ float warp_sums[8];
    if (lane == 0) warp_sums[threadIdx.x >> 5] = s;
    __syncthreads();
    if (threadIdx.x < 8) {
        float v = warp_sums[threadIdx.x];
#pragma unroll
        for (int off = 4; off; off >>= 1)
            v += __shfl_down_sync(0xffu, v, off);
        if (threadIdx.x == 0) atomicAdd(out, v * invE);
    }
}

extern "C" void kernel_launch(void* const* d_in, const int* in_sizes, int n_in,
                              void* d_out, int out_size) {
    const float2* pts = (const float2*)d_in[0];
    const void* skel = d_in[1];
    const float* initl = (const float*)d_in[2];
    float* out = (float*)d_out;

    int N = in_sizes[0] / 128;  // B=64 frames, 2 coords
    int E = in_sizes[2];

    int tblocks = (N + 31) / 32;
    int pblocks = (E_PAD + 255) / 256;
    transpose_kernel<<<tblocks + pblocks, 256>>>(
        pts, (const unsigned*)skel, initl, out, N, E, tblocks);
    loss_kernel<<<888, 256>>>(out, E, 1.0f / (float)E);
}